// round 8
// baseline (speedup 1.0000x reference)
#include <cuda_runtime.h>

#define NTOT       1572864      // 3 * 32 * 128 * 128 scores
#define NQ         393216       // NTOT / 4
#define W_DIM      128
#define H_DIM      128
#define CH_STRIDE  524288       // 32*128*128 (per-channel stride)
#define PRE_N      2000
#define POST_N     300
#define CAND_CAP   4096
#define NMS_T      0.7f
#define HBINS      262144       // 2^18 coarse bins
#define BIN_SHIFT  14           // key >> 14 -> bin
#define NB         512          // persistent blocks (capacity: 4/SM * 148 = 592)
#define NTHREADS   131072       // NB * 256

// ---------------- scratch (device globals; zero-initialized at load) -------
__device__ unsigned g_hist[HBINS];
__device__ unsigned g_thresh;
__device__ unsigned g_candCount;
__device__ unsigned long long g_cand[CAND_CAP];
__device__ int g_topIdx[PRE_N];

__device__ float g_bx1[PRE_N], g_by1[PRE_N], g_bz1[PRE_N];
__device__ float g_bx2[PRE_N], g_by2[PRE_N], g_bz2[PRE_N];
__device__ float g_vol[PRE_N], g_sc[PRE_N];

__device__ unsigned g_supp32[64];
__device__ unsigned long long g_mask[PRE_N * 32];

// grid barrier state (generation-based; g_barGen persists across replays)
__device__ unsigned g_barCount;
__device__ volatile unsigned g_barGen;

__device__ __forceinline__ unsigned mapKey(float f) {
    unsigned b = __float_as_uint(f);
    return b ^ ((b & 0x80000000u) ? 0xFFFFFFFFu : 0x80000000u);
}

__device__ __forceinline__ void gridBar() {
    __threadfence();                 // publish this block's writes
    __syncthreads();
    if (threadIdx.x == 0) {
        unsigned gen = g_barGen;
        if (atomicAdd(&g_barCount, 1u) == (unsigned)(gridDim.x - 1)) {
            g_barCount = 0u;
            __threadfence();
            g_barGen = gen + 1u;     // release
        } else {
            while (g_barGen == gen) { }
            __threadfence();
        }
    }
    __syncthreads();
}

__global__ void __launch_bounds__(256, 4)
k_all(const float4* __restrict__ sc4, const float* __restrict__ sc,
      const float* __restrict__ dl, const float* __restrict__ imi,
      const float* __restrict__ anc, float* __restrict__ out, int out_size) {
    __shared__ unsigned long long sKeys[CAND_CAP];   // 32 KB (rank phase)
    __shared__ unsigned sChunkF[256];                // scan chunk sums
    __shared__ int sBC; __shared__ unsigned sAboveC;
    __shared__ int sKeep[POST_N]; __shared__ int sKept;

    const int tid = threadIdx.x;
    const int gtid = blockIdx.x * 256 + tid;

    // ---------- P1: coarse 18-bit histogram (3 strided iters) ---------------
    #pragma unroll
    for (int it = 0; it < 3; it++) {
        int t = gtid + it * NTHREADS;          // < NQ exactly
        float4 v = __ldg(&sc4[t]);
        atomicAdd(&g_hist[mapKey(v.x) >> BIN_SHIFT], 1u);
        atomicAdd(&g_hist[mapKey(v.y) >> BIN_SHIFT], 1u);
        atomicAdd(&g_hist[mapKey(v.z) >> BIN_SHIFT], 1u);
        atomicAdd(&g_hist[mapKey(v.w) >> BIN_SHIFT], 1u);
    }
    gridBar();   // B1

    // ---------- P2: find boundary bin (block 0 only) ------------------------
    if (blockIdx.x == 0) {
        int w = tid >> 5, l = tid & 31;
        int seg = w * 32768;                  // 8 warps x 32768 bins
        for (int c = 0; c < 32; c++) {
            unsigned cs = 0;
            int base = seg + c * 1024 + l;
            #pragma unroll 8
            for (int k = 0; k < 32; k++) cs += g_hist[base + k * 32];
            #pragma unroll
            for (int d = 16; d > 0; d >>= 1) cs += __shfl_down_sync(0xFFFFFFFFu, cs, d);
            if (l == 0) sChunkF[w * 32 + c] = cs;   // chunk cc = bins [cc*1024, +1024)
        }
        __syncthreads();
        if (tid < 32) {
            int l = tid;
            unsigned s8 = 0;
            #pragma unroll
            for (int k = 0; k < 8; k++) s8 += sChunkF[l * 8 + k];
            unsigned suf = s8;
            #pragma unroll
            for (int d = 1; d < 32; d <<= 1) {
                unsigned v = __shfl_down_sync(0xFFFFFFFFu, suf, d);
                if (l + d < 32) suf += v;
            }
            unsigned above = suf - s8;
            if (above < PRE_N && suf >= PRE_N) {       // unique lane
                unsigned running = above;
                for (int k = 7; k >= 0; k--) {
                    unsigned h = sChunkF[l * 8 + k];
                    if (running + h >= PRE_N) { sBC = l * 8 + k; sAboveC = running; break; }
                    running += h;
                }
            }
        }
        __syncthreads();
        if (tid < 32) {
            int l = tid;
            int base = sBC * 1024;
            unsigned running = sAboveC;
            for (int gI = 31; gI >= 0; gI--) {
                unsigned h = g_hist[base + gI * 32 + l];
                unsigned suf = h;
                #pragma unroll
                for (int d = 1; d < 32; d <<= 1) {
                    unsigned v = __shfl_down_sync(0xFFFFFFFFu, suf, d);
                    if (l + d < 32) suf += v;
                }
                unsigned bal = __ballot_sync(0xFFFFFFFFu, running + suf >= PRE_N);
                if (bal) {
                    if (l == 31 - __clz(bal))
                        g_thresh = (unsigned)(base + gI * 32 + l) << BIN_SHIFT;
                    break;
                }
                running += __shfl_sync(0xFFFFFFFFu, suf, 0);
            }
            if (l == 0) g_candCount = 0u;
        }
    }
    gridBar();   // B2

    // ---------- P3: collect candidates (transposed idx = pos*3 + a) --------
    {
        unsigned T = g_thresh;
        #pragma unroll
        for (int it = 0; it < 3; it++) {
            int t = gtid + it * NTHREADS;
            float4 v = __ldg(&sc4[t]);
            int base = 4 * t;
            int a = base / CH_STRIDE;
            int pos = base - a * CH_STRIDE;
            unsigned k0 = mapKey(v.x), k1 = mapKey(v.y), k2 = mapKey(v.z), k3 = mapKey(v.w);
            if (k0 >= T) { unsigned p = atomicAdd(&g_candCount, 1u); if (p < CAND_CAP) g_cand[p] = ((unsigned long long)(~k0) << 32) | (unsigned)((pos + 0) * 3 + a); }
            if (k1 >= T) { unsigned p = atomicAdd(&g_candCount, 1u); if (p < CAND_CAP) g_cand[p] = ((unsigned long long)(~k1) << 32) | (unsigned)((pos + 1) * 3 + a); }
            if (k2 >= T) { unsigned p = atomicAdd(&g_candCount, 1u); if (p < CAND_CAP) g_cand[p] = ((unsigned long long)(~k2) << 32) | (unsigned)((pos + 2) * 3 + a); }
            if (k3 >= T) { unsigned p = atomicAdd(&g_candCount, 1u); if (p < CAND_CAP) g_cand[p] = ((unsigned long long)(~k3) << 32) | (unsigned)((pos + 3) * 3 + a); }
        }
    }
    gridBar();   // B3

    // ---------- P4: rank-and-scatter (blocks 0..15, exact order) ------------
    if (blockIdx.x < 16) {
        int cc = (int)(*(volatile unsigned*)&g_candCount);
        if (cc > CAND_CAP) cc = CAND_CAP;
        for (int i = tid; i < cc; i += 256) sKeys[i] = g_cand[i];
        __syncthreads();
        int i = blockIdx.x * 256 + tid;
        if (i < cc) {
            unsigned long long k = sKeys[i];
            int r = 0, j = 0;
            for (; j + 4 <= cc; j += 4) {
                r += (sKeys[j]     < k);
                r += (sKeys[j + 1] < k);
                r += (sKeys[j + 2] < k);
                r += (sKeys[j + 3] < k);
            }
            for (; j < cc; j++) r += (sKeys[j] < k);
            if (r < PRE_N) g_topIdx[r] = (int)(k & 0xFFFFFFFFu);
        }
    }
    gridBar();   // B4

    // ---------- P5: box decode + validity (blocks 0..7) ---------------------
    if (blockIdx.x < 8) {
        int r = blockIdx.x * 256 + tid;       // covers 2048
        bool valid = false;
        if (r < PRE_N) {
            int idx = g_topIdx[r];
            int a   = idx % 3;
            int pos = idx / 3;
            int wl  = pos % W_DIM;
            int hl  = (pos / W_DIM) % H_DIM;
            int sl  = pos / (W_DIM * H_DIM);
            float shx = wl * 4.0f, shy = hl * 4.0f, shz = sl * 4.0f;
            float ax1 = anc[a*6+0] + shx, ay1 = anc[a*6+1] + shy, az1 = anc[a*6+2] + shz;
            float ax2 = anc[a*6+3] + shx, ay2 = anc[a*6+4] + shy, az2 = anc[a*6+5] + shz;

            const float* db = dl + (size_t)(6 * a) * CH_STRIDE + pos;
            float d0 = db[0];
            float d1 = db[(size_t)CH_STRIDE];
            float d2 = db[(size_t)2 * CH_STRIDE];
            float d3 = db[(size_t)3 * CH_STRIDE];
            float d4 = db[(size_t)4 * CH_STRIDE];
            float d5 = db[(size_t)5 * CH_STRIDE];

            float w_ = ax2 - ax1 + 1.0f, h_ = ay2 - ay1 + 1.0f, dd = az2 - az1 + 1.0f;
            float cx = ax1 + 0.5f * w_, cy = ay1 + 0.5f * h_, cz = az1 + 0.5f * dd;
            float pcx = d0 * w_ + cx, pcy = d1 * h_ + cy, pcz = d2 * dd + cz;
            float pw = expf(d3) * w_, ph = expf(d4) * h_, pd = expf(d5) * dd;

            float slices = imi[0], height = imi[1], width = imi[2], scale = imi[3];
            float x1 = fminf(fmaxf(pcx - 0.5f * pw, 0.0f), width  - 1.0f);
            float y1 = fminf(fmaxf(pcy - 0.5f * ph, 0.0f), height - 1.0f);
            float z1 = fminf(fmaxf(pcz - 0.5f * pd, 0.0f), slices - 1.0f);
            float x2 = fminf(fmaxf(pcx + 0.5f * pw - 1.0f, 0.0f), width  - 1.0f);
            float y2 = fminf(fmaxf(pcy + 0.5f * ph - 1.0f, 0.0f), height - 1.0f);
            float z2 = fminf(fmaxf(pcz + 0.5f * pd - 1.0f, 0.0f), slices - 1.0f);

            g_bx1[r] = x1; g_by1[r] = y1; g_bz1[r] = z1;
            g_bx2[r] = x2; g_by2[r] = y2; g_bz2[r] = z2;
            g_vol[r] = (x2 - x1 + 1.0f) * (y2 - y1 + 1.0f) * (z2 - z1 + 1.0f);
            g_sc[r]  = sc[(size_t)a * CH_STRIDE + pos];

            float ss = x2 - x1 + 1.0f;
            float xc = x1 + ss * 0.5f, yc = y1 + ss * 0.5f, zc = z1 + ss * 0.5f;
            valid = (ss >= 8.0f * scale) && (xc < width) && (yc < height) && (zc < slices);
        }
        unsigned suppressed = __ballot_sync(0xFFFFFFFFu, !valid);
        if ((tid & 31) == 0) g_supp32[r >> 5] = suppressed;
    }
    gridBar();   // B5

    // ---------- P6: IoU suppression bitmask + hist re-zero ------------------
    // NO __syncthreads() in this phase (tile roles vary within a block).
    {
        g_hist[gtid] = 0u;
        g_hist[gtid + NTHREADS] = 0u;
        int grp = blockIdx.x * 4 + (tid >> 6);  // 2048 groups >= 1024 tiles
        int t64 = tid & 63;
        if (grp < 1024) {
            int by = grp >> 5, bx = grp & 31;
            int i = by * 64 + t64;
            if (i < PRE_N) {
                if (bx < by) {                   // whole tile has j < i
                    g_mask[(size_t)i * 32 + bx] = 0ULL;
                } else {
                    float x1 = g_bx1[i], y1 = g_by1[i], z1 = g_bz1[i];
                    float x2 = g_bx2[i], y2 = g_by2[i], z2 = g_bz2[i];
                    float v  = g_vol[i];
                    unsigned long long m = 0ULL;
                    int jbase = bx * 64;
                    int jmax = PRE_N - jbase; if (jmax > 64) jmax = 64;
                    for (int c = 0; c < jmax; c++) {
                        int jg = jbase + c;
                        if (jg <= i) continue;
                        // c is uniform across the group -> broadcast loads
                        float jx1 = __ldg(&g_bx1[jg]), jy1 = __ldg(&g_by1[jg]);
                        float jz1 = __ldg(&g_bz1[jg]), jx2 = __ldg(&g_bx2[jg]);
                        float jy2 = __ldg(&g_by2[jg]), jz2 = __ldg(&g_bz2[jg]);
                        float jv  = __ldg(&g_vol[jg]);
                        float iw = fmaxf(fminf(x2, jx2) - fmaxf(x1, jx1) + 1.0f, 0.0f);
                        float ih = fmaxf(fminf(y2, jy2) - fmaxf(y1, jy1) + 1.0f, 0.0f);
                        float id = fmaxf(fminf(z2, jz2) - fmaxf(z1, jz1) + 1.0f, 0.0f);
                        float inter = iw * ih * id;
                        float iou = inter / (v + jv - inter);
                        if (iou > NMS_T) m |= (1ULL << c);
                    }
                    g_mask[(size_t)i * 32 + bx] = m;
                }
            }
        }
    }
    gridBar();   // B6

    // ---------- P7: greedy NMS reduce + output (block 0) --------------------
    if (blockIdx.x != 0) return;
    if (tid < 32) {
        int lane = tid;
        unsigned long long remv =
            ((unsigned long long)g_supp32[2 * lane + 1] << 32) | g_supp32[2 * lane];
        unsigned long long pf[8];
        #pragma unroll
        for (int d = 0; d < 8; d++) pf[d] = g_mask[(size_t)d * 32 + lane];
        int kept = 0;
        int curWI = 0;
        unsigned long long curw = __shfl_sync(0xFFFFFFFFu, remv, 0);
        for (int i = 0; i < PRE_N; i++) {
            unsigned long long cur = pf[i & 7];
            if (i + 8 < PRE_N) pf[i & 7] = g_mask[(size_t)(i + 8) * 32 + lane];
            int wi = i >> 6;
            if (wi != curWI) { curw = __shfl_sync(0xFFFFFFFFu, remv, wi); curWI = wi; }
            if (!((curw >> (i & 63)) & 1ULL)) {
                remv |= cur;
                curw = __shfl_sync(0xFFFFFFFFu, remv, wi);
                if (lane == 0) sKeep[kept] = i;
                kept++;
                if (kept == POST_N) break;
            }
        }
        if (lane == 0) sKept = kept;
        __syncwarp();
        kept = sKept;
        for (int s = lane; s < POST_N; s += 32) {
            float b0, b1, b2, b3, b4, b5, scv, kidx, vld;
            if (s < kept) {
                int i = sKeep[s];
                b0 = g_bx1[i]; b1 = g_by1[i]; b2 = g_bz1[i];
                b3 = g_bx2[i]; b4 = g_by2[i]; b5 = g_bz2[i];
                scv = g_sc[i]; kidx = (float)g_topIdx[i]; vld = 1.0f;
            } else {
                b0 = b1 = b2 = b3 = b4 = b5 = 0.0f;
                scv = 0.0f; kidx = -1.0f; vld = 0.0f;
            }
            int base = s * 7;
            out[base + 0] = 0.0f;
            out[base + 1] = b0; out[base + 2] = b1; out[base + 3] = b2;
            out[base + 4] = b3; out[base + 5] = b4; out[base + 6] = b5;
            if (out_size >= POST_N * 7 + POST_N) out[POST_N * 7 + s] = scv;
            if (out_size >= POST_N * 8 + POST_N) out[POST_N * 8 + s] = kidx;
            if (out_size >= POST_N * 9 + POST_N) out[POST_N * 9 + s] = vld;
        }
    }
}

// ---------------- launcher --------------------------------------------------
extern "C" void kernel_launch(void* const* d_in, const int* in_sizes, int n_in,
                              void* d_out, int out_size) {
    const float*  sc  = (const float*)d_in[0];
    const float4* sc4 = (const float4*)d_in[0];
    const float*  dl  = (const float*)d_in[1];
    const float*  imi = (const float*)d_in[2];
    const float*  anc = (const float*)d_in[3];
    float* out = (float*)d_out;

    k_all<<<NB, 256>>>(sc4, sc, dl, imi, anc, out, out_size);
}

// round 10
// speedup vs baseline: 1.0698x; 1.0698x over previous
#include <cuda_runtime.h>

#define NTOT       1572864      // 3 * 32 * 128 * 128 scores
#define NQ         393216       // NTOT / 4
#define W_DIM      128
#define H_DIM      128
#define CH_STRIDE  524288       // 32*128*128 (per-channel stride)
#define PRE_N      2000
#define POST_N     300
#define CAND_CAP   4096
#define NMS_T      0.7f
#define HBINS      262144       // 2^18 coarse bins
#define BIN_SHIFT  14           // key >> 14 -> bin

// ---------------- scratch (device globals; zero-initialized at load) -------
__device__ unsigned g_hist[HBINS];
__device__ unsigned g_histDone;    // last-block detector; reset by scan tail
__device__ unsigned g_thresh;
__device__ unsigned g_candCount;
__device__ unsigned long long g_cand[CAND_CAP];
__device__ int g_topIdx[PRE_N];

__device__ float g_bx1[PRE_N], g_by1[PRE_N], g_bz1[PRE_N];
__device__ float g_bx2[PRE_N], g_by2[PRE_N], g_bz2[PRE_N];
__device__ float g_vol[PRE_N], g_sc[PRE_N];

__device__ unsigned g_supp32[64];
__device__ unsigned long long g_mask[PRE_N * 32];

__device__ __forceinline__ unsigned mapKey(float f) {
    unsigned b = __float_as_uint(f);
    return b ^ ((b & 0x80000000u) ? 0xFFFFFFFFu : 0x80000000u);
}

// ---------------- 1) histogram + (last block) boundary scan -----------------
__global__ void k_histscan(const float4* __restrict__ sc4) {
    int t = blockIdx.x * 256 + threadIdx.x;      // covers NQ exactly (1536x256)
    float4 v = __ldg(&sc4[t]);
    atomicAdd(&g_hist[mapKey(v.x) >> BIN_SHIFT], 1u);
    atomicAdd(&g_hist[mapKey(v.y) >> BIN_SHIFT], 1u);
    atomicAdd(&g_hist[mapKey(v.z) >> BIN_SHIFT], 1u);
    atomicAdd(&g_hist[mapKey(v.w) >> BIN_SHIFT], 1u);

    __shared__ int sLast;
    __threadfence();
    __syncthreads();
    if (threadIdx.x == 0)
        sLast = (atomicAdd(&g_histDone, 1u) == (unsigned)(gridDim.x - 1));
    __syncthreads();
    if (!sLast) return;

    // ---- this block alone: find boundary bin for rank PRE_N (from top) ----
    __shared__ unsigned sChunkF[256];
    __shared__ int sBC; __shared__ unsigned sAboveC;
    int tid = threadIdx.x;
    int w = tid >> 5, l = tid & 31;
    int seg = w * 32768;                  // 8 warps x 32768 bins
    for (int c = 0; c < 32; c++) {
        unsigned cs = 0;
        int base = seg + c * 1024 + l;
        #pragma unroll 8
        for (int k = 0; k < 32; k++) cs += g_hist[base + k * 32];
        #pragma unroll
        for (int d = 16; d > 0; d >>= 1) cs += __shfl_down_sync(0xFFFFFFFFu, cs, d);
        if (l == 0) sChunkF[w * 32 + c] = cs;   // chunk cc = bins [cc*1024,+1024)
    }
    __syncthreads();
    if (tid < 32) {
        unsigned s8 = 0;
        #pragma unroll
        for (int k = 0; k < 8; k++) s8 += sChunkF[l * 8 + k];
        unsigned suf = s8;
        #pragma unroll
        for (int d = 1; d < 32; d <<= 1) {
            unsigned vv = __shfl_down_sync(0xFFFFFFFFu, suf, d);
            if (l + d < 32) suf += vv;
        }
        unsigned above = suf - s8;
        if (above < PRE_N && suf >= PRE_N) {       // unique lane
            unsigned running = above;
            for (int k = 7; k >= 0; k--) {
                unsigned h = sChunkF[l * 8 + k];
                if (running + h >= PRE_N) { sBC = l * 8 + k; sAboveC = running; break; }
                running += h;
            }
        }
    }
    __syncthreads();
    if (tid < 32) {
        int base = sBC * 1024;
        unsigned running = sAboveC;
        for (int gI = 31; gI >= 0; gI--) {
            unsigned h = g_hist[base + gI * 32 + l];
            unsigned suf = h;
            #pragma unroll
            for (int d = 1; d < 32; d <<= 1) {
                unsigned vv = __shfl_down_sync(0xFFFFFFFFu, suf, d);
                if (l + d < 32) suf += vv;
            }
            unsigned bal = __ballot_sync(0xFFFFFFFFu, running + suf >= PRE_N);
            if (bal) {
                if (l == 31 - __clz(bal))
                    g_thresh = (unsigned)(base + gI * 32 + l) << BIN_SHIFT;
                break;
            }
            running += __shfl_sync(0xFFFFFFFFu, suf, 0);
        }
        if (l == 0) { g_candCount = 0u; g_histDone = 0u; }
    }
}

// ---------------- 2) collect candidates (transposed idx = pos*3 + a) --------
__global__ void k_collect(const float4* __restrict__ sc4) {
    unsigned T = g_thresh;
    int t = blockIdx.x * 256 + threadIdx.x;
    float4 v = __ldg(&sc4[t]);
    int base = 4 * t;
    int a = base / CH_STRIDE;            // all 4 elements share the channel
    int pos = base - a * CH_STRIDE;
    unsigned k0 = mapKey(v.x), k1 = mapKey(v.y), k2 = mapKey(v.z), k3 = mapKey(v.w);
    if (k0 >= T) { unsigned p = atomicAdd(&g_candCount, 1u); if (p < CAND_CAP) g_cand[p] = ((unsigned long long)(~k0) << 32) | (unsigned)((pos + 0) * 3 + a); }
    if (k1 >= T) { unsigned p = atomicAdd(&g_candCount, 1u); if (p < CAND_CAP) g_cand[p] = ((unsigned long long)(~k1) << 32) | (unsigned)((pos + 1) * 3 + a); }
    if (k2 >= T) { unsigned p = atomicAdd(&g_candCount, 1u); if (p < CAND_CAP) g_cand[p] = ((unsigned long long)(~k2) << 32) | (unsigned)((pos + 2) * 3 + a); }
    if (k3 >= T) { unsigned p = atomicAdd(&g_candCount, 1u); if (p < CAND_CAP) g_cand[p] = ((unsigned long long)(~k3) << 32) | (unsigned)((pos + 3) * 3 + a); }
}

// ---------------- 3) rank-and-scatter: 128 blocks, warp-per-4-keys ----------
__global__ void k_rank() {
    __shared__ unsigned long long sKeys[CAND_CAP];
    int tid = threadIdx.x;
    int cc = (int)g_candCount; if (cc > CAND_CAP) cc = CAND_CAP;
    for (int i = tid; i < cc; i += 256) sKeys[i] = g_cand[i];
    __syncthreads();
    int w = tid >> 5, l = tid & 31;
    int kbase = blockIdx.x * 32 + w * 4;      // this warp owns keys kbase..+3
    if (kbase >= cc) return;
    unsigned long long k0 = sKeys[kbase];
    unsigned long long k1 = (kbase + 1 < cc) ? sKeys[kbase + 1] : 0xFFFFFFFFFFFFFFFFULL;
    unsigned long long k2 = (kbase + 2 < cc) ? sKeys[kbase + 2] : 0xFFFFFFFFFFFFFFFFULL;
    unsigned long long k3 = (kbase + 3 < cc) ? sKeys[kbase + 3] : 0xFFFFFFFFFFFFFFFFULL;
    int r0 = 0, r1 = 0, r2 = 0, r3 = 0;
    for (int j = l; j < cc; j += 32) {
        unsigned long long kj = sKeys[j];
        r0 += (kj < k0); r1 += (kj < k1); r2 += (kj < k2); r3 += (kj < k3);
    }
    #pragma unroll
    for (int d = 16; d > 0; d >>= 1) {
        r0 += __shfl_down_sync(0xFFFFFFFFu, r0, d);
        r1 += __shfl_down_sync(0xFFFFFFFFu, r1, d);
        r2 += __shfl_down_sync(0xFFFFFFFFu, r2, d);
        r3 += __shfl_down_sync(0xFFFFFFFFu, r3, d);
    }
    if (l == 0) {
        if (r0 < PRE_N)                    g_topIdx[r0] = (int)(k0 & 0xFFFFFFFFu);
        if (kbase + 1 < cc && r1 < PRE_N)  g_topIdx[r1] = (int)(k1 & 0xFFFFFFFFu);
        if (kbase + 2 < cc && r2 < PRE_N)  g_topIdx[r2] = (int)(k2 & 0xFFFFFFFFu);
        if (kbase + 3 < cc && r3 < PRE_N)  g_topIdx[r3] = (int)(k3 & 0xFFFFFFFFu);
    }
}

// ---------------- 4) box decode + validity ----------------------------------
__global__ void k_transform(const float* __restrict__ sc,
                            const float* __restrict__ dl,
                            const float* __restrict__ imi,
                            const float* __restrict__ anc) {
    int r = blockIdx.x * 256 + threadIdx.x;    // 8x256 covers 2048
    bool valid = false;
    if (r < PRE_N) {
        int idx = g_topIdx[r];            // transposed flat index
        int a   = idx % 3;
        int pos = idx / 3;
        int wl  = pos % W_DIM;
        int hl  = (pos / W_DIM) % H_DIM;
        int sl  = pos / (W_DIM * H_DIM);
        float shx = wl * 4.0f, shy = hl * 4.0f, shz = sl * 4.0f;
        float ax1 = anc[a*6+0] + shx, ay1 = anc[a*6+1] + shy, az1 = anc[a*6+2] + shz;
        float ax2 = anc[a*6+3] + shx, ay2 = anc[a*6+4] + shy, az2 = anc[a*6+5] + shz;

        const float* db = dl + (size_t)(6 * a) * CH_STRIDE + pos;
        float d0 = db[0];
        float d1 = db[(size_t)CH_STRIDE];
        float d2 = db[(size_t)2 * CH_STRIDE];
        float d3 = db[(size_t)3 * CH_STRIDE];
        float d4 = db[(size_t)4 * CH_STRIDE];
        float d5 = db[(size_t)5 * CH_STRIDE];

        float w_ = ax2 - ax1 + 1.0f, h_ = ay2 - ay1 + 1.0f, dd = az2 - az1 + 1.0f;
        float cx = ax1 + 0.5f * w_, cy = ay1 + 0.5f * h_, cz = az1 + 0.5f * dd;
        float pcx = d0 * w_ + cx, pcy = d1 * h_ + cy, pcz = d2 * dd + cz;
        float pw = expf(d3) * w_, ph = expf(d4) * h_, pd = expf(d5) * dd;

        float slices = imi[0], height = imi[1], width = imi[2], scale = imi[3];
        float x1 = fminf(fmaxf(pcx - 0.5f * pw, 0.0f), width  - 1.0f);
        float y1 = fminf(fmaxf(pcy - 0.5f * ph, 0.0f), height - 1.0f);
        float z1 = fminf(fmaxf(pcz - 0.5f * pd, 0.0f), slices - 1.0f);
        float x2 = fminf(fmaxf(pcx + 0.5f * pw - 1.0f, 0.0f), width  - 1.0f);
        float y2 = fminf(fmaxf(pcy + 0.5f * ph - 1.0f, 0.0f), height - 1.0f);
        float z2 = fminf(fmaxf(pcz + 0.5f * pd - 1.0f, 0.0f), slices - 1.0f);

        g_bx1[r] = x1; g_by1[r] = y1; g_bz1[r] = z1;
        g_bx2[r] = x2; g_by2[r] = y2; g_bz2[r] = z2;
        g_vol[r] = (x2 - x1 + 1.0f) * (y2 - y1 + 1.0f) * (z2 - z1 + 1.0f);
        g_sc[r]  = sc[(size_t)a * CH_STRIDE + pos];

        float ss = x2 - x1 + 1.0f;
        float xc = x1 + ss * 0.5f, yc = y1 + ss * 0.5f, zc = z1 + ss * 0.5f;
        valid = (ss >= 8.0f * scale) && (xc < width) && (yc < height) && (zc < slices);
    }
    unsigned suppressed = __ballot_sync(0xFFFFFFFFu, !valid);
    if ((threadIdx.x & 31) == 0) g_supp32[r >> 5] = suppressed;
}

// ---------------- 5) IoU suppression bitmask + hist re-zero ------------------
__global__ void k_mask() {
    int tid = threadIdx.x;
    int gtid = blockIdx.x * 256 + tid;         // 512x256 = 131072
    g_hist[gtid] = 0u;
    g_hist[gtid + 131072] = 0u;
    int grp = blockIdx.x * 4 + (tid >> 6);     // 2048 groups >= 1024 tiles
    int t64 = tid & 63;
    if (grp >= 1024) return;
    int by = grp >> 5, bx = grp & 31;
    int i = by * 64 + t64;
    if (i >= PRE_N) return;
    if (bx < by) {                              // whole tile has j < i
        g_mask[(size_t)i * 32 + bx] = 0ULL;
        return;
    }
    float x1 = g_bx1[i], y1 = g_by1[i], z1 = g_bz1[i];
    float x2 = g_bx2[i], y2 = g_by2[i], z2 = g_bz2[i];
    float v  = g_vol[i];
    unsigned long long m = 0ULL;
    int jbase = bx * 64;
    int jmax = PRE_N - jbase; if (jmax > 64) jmax = 64;
    for (int c = 0; c < jmax; c++) {
        int jg = jbase + c;
        if (jg <= i) continue;
        // c uniform across the 64-thread group -> broadcast loads (L1-cached)
        float jx1 = __ldg(&g_bx1[jg]), jy1 = __ldg(&g_by1[jg]);
        float jz1 = __ldg(&g_bz1[jg]), jx2 = __ldg(&g_bx2[jg]);
        float jy2 = __ldg(&g_by2[jg]), jz2 = __ldg(&g_bz2[jg]);
        float jv  = __ldg(&g_vol[jg]);
        float iw = fmaxf(fminf(x2, jx2) - fmaxf(x1, jx1) + 1.0f, 0.0f);
        float ih = fmaxf(fminf(y2, jy2) - fmaxf(y1, jy1) + 1.0f, 0.0f);
        float id = fmaxf(fminf(z2, jz2) - fmaxf(z1, jz1) + 1.0f, 0.0f);
        float inter = iw * ih * id;
        float iou = inter / (v + jv - inter);
        if (iou > NMS_T) m |= (1ULL << c);
    }
    g_mask[(size_t)i * 32 + bx] = m;
}

// ---------------- 6) greedy NMS reduce (1 warp) + output --------------------
__global__ void k_reduceout(float* __restrict__ out, int out_size) {
    __shared__ int sKeep[POST_N];
    __shared__ int sKept;
    int tid = threadIdx.x;                     // 256 threads
    if (tid < 32) {
        int lane = tid;
        unsigned long long remv =
            ((unsigned long long)g_supp32[2 * lane + 1] << 32) | g_supp32[2 * lane];
        unsigned long long pf[8];
        #pragma unroll
        for (int d = 0; d < 8; d++) pf[d] = g_mask[(size_t)d * 32 + lane];
        int kept = 0;
        int curWI = 0;
        unsigned long long curw = __shfl_sync(0xFFFFFFFFu, remv, 0);
        for (int i = 0; i < PRE_N; i++) {
            unsigned long long cur = pf[i & 7];
            if (i + 8 < PRE_N) pf[i & 7] = g_mask[(size_t)(i + 8) * 32 + lane];
            int wi = i >> 6;
            if (wi != curWI) { curw = __shfl_sync(0xFFFFFFFFu, remv, wi); curWI = wi; }
            if (!((curw >> (i & 63)) & 1ULL)) {
                remv |= cur;
                curw = __shfl_sync(0xFFFFFFFFu, remv, wi);
                if (lane == 0) sKeep[kept] = i;
                kept++;
                if (kept == POST_N) break;
            }
        }
        if (lane == 0) sKept = kept;
    }
    __syncthreads();
    int kept = sKept;
    for (int s = tid; s < POST_N; s += 256) {
        float b0, b1, b2, b3, b4, b5, scv, kidx, vld;
        if (s < kept) {
            int i = sKeep[s];
            b0 = g_bx1[i]; b1 = g_by1[i]; b2 = g_bz1[i];
            b3 = g_bx2[i]; b4 = g_by2[i]; b5 = g_bz2[i];
            scv = g_sc[i]; kidx = (float)g_topIdx[i]; vld = 1.0f;
        } else {
            b0 = b1 = b2 = b3 = b4 = b5 = 0.0f;
            scv = 0.0f; kidx = -1.0f; vld = 0.0f;
        }
        int base = s * 7;
        out[base + 0] = 0.0f;
        out[base + 1] = b0; out[base + 2] = b1; out[base + 3] = b2;
        out[base + 4] = b3; out[base + 5] = b4; out[base + 6] = b5;
        if (out_size >= POST_N * 7 + POST_N) out[POST_N * 7 + s] = scv;
        if (out_size >= POST_N * 8 + POST_N) out[POST_N * 8 + s] = kidx;
        if (out_size >= POST_N * 9 + POST_N) out[POST_N * 9 + s] = vld;
    }
}

// ---------------- launcher --------------------------------------------------
extern "C" void kernel_launch(void* const* d_in, const int* in_sizes, int n_in,
                              void* d_out, int out_size) {
    const float*  sc  = (const float*)d_in[0];
    const float4* sc4 = (const float4*)d_in[0];
    const float*  dl  = (const float*)d_in[1];
    const float*  imi = (const float*)d_in[2];
    const float*  anc = (const float*)d_in[3];
    float* out = (float*)d_out;

    k_histscan <<<1536, 256>>>(sc4);
    k_collect  <<<1536, 256>>>(sc4);
    k_rank     <<<128, 256>>>();
    k_transform<<<8, 256>>>(sc, dl, imi, anc);
    k_mask     <<<512, 256>>>();
    k_reduceout<<<1, 256>>>(out, out_size);
}

// round 13
// speedup vs baseline: 1.6500x; 1.5423x over previous
#include <cuda_runtime.h>

#define NTOT       1572864      // 3 * 32 * 128 * 128 scores
#define NQ         393216       // NTOT / 4
#define W_DIM      128
#define H_DIM      128
#define CH_STRIDE  524288       // 32*128*128 (per-channel stride)
#define PRE_N      2000
#define POST_N     300
#define CAND_CAP   4096
#define NMS_T      0.7f
#define CACHE_N    640          // mask rows cached in smem for reduce
#define HBINS      262144       // 2^18 coarse bins
#define BIN_SHIFT  14           // key >> 14 -> bin

// ---------------- scratch (device globals; zero-initialized at load) -------
__device__ unsigned g_hist[HBINS];
__device__ unsigned g_thresh;
__device__ unsigned g_candCount;
__device__ unsigned long long g_cand[CAND_CAP];
__device__ int g_topIdx[PRE_N];

__device__ float g_bx1[PRE_N], g_by1[PRE_N], g_bz1[PRE_N];
__device__ float g_bx2[PRE_N], g_by2[PRE_N], g_bz2[PRE_N];
__device__ float g_vol[PRE_N], g_sc[PRE_N];

__device__ unsigned g_supp32[64];                 // initial suppression bits
__device__ unsigned long long g_mask[PRE_N * 32]; // NMS suppression bitmask rows

__device__ __forceinline__ unsigned mapKey(float f) {
    unsigned b = __float_as_uint(f);
    return b ^ ((b & 0x80000000u) ? 0xFFFFFFFFu : 0x80000000u);
}

// ---------------- 1) coarse 18-bit histogram --------------------------------
__global__ void k_hist(const float4* __restrict__ sc) {
    int t = blockIdx.x * blockDim.x + threadIdx.x;   // 0..NQ-1 exactly
    float4 v = __ldg(&sc[t]);
    atomicAdd(&g_hist[mapKey(v.x) >> BIN_SHIFT], 1u);
    atomicAdd(&g_hist[mapKey(v.y) >> BIN_SHIFT], 1u);
    atomicAdd(&g_hist[mapKey(v.z) >> BIN_SHIFT], 1u);
    atomicAdd(&g_hist[mapKey(v.w) >> BIN_SHIFT], 1u);
}

// ---------------- 2) find boundary bin (coalesced, warp-segmented) ----------
__global__ void k_scan() {
    __shared__ unsigned warpTot[32];
    __shared__ unsigned suffAbove[32];
    __shared__ int boundWarp;
    int t = threadIdx.x;             // 1024 threads = 32 warps
    int w = t >> 5, l = t & 31;
    if (t == 0) { g_candCount = 0u; boundWarp = -1; }
    int seg = w * 8192;              // warp w owns bins [seg, seg+8192)
    unsigned s = 0;
    #pragma unroll 16
    for (int i = 0; i < 256; i++) s += g_hist[seg + i * 32 + l];   // coalesced
    #pragma unroll
    for (int d = 16; d > 0; d >>= 1) s += __shfl_down_sync(0xFFFFFFFFu, s, d);
    if (l == 0) warpTot[w] = s;
    __syncthreads();
    if (w == 0) {
        unsigned tot = warpTot[l];
        unsigned suf = tot;
        #pragma unroll
        for (int d = 1; d < 32; d <<= 1) {
            unsigned v = __shfl_down_sync(0xFFFFFFFFu, suf, d);
            if (l + d < 32) suf += v;
        }
        unsigned above = suf - tot;
        if (above < PRE_N && suf >= PRE_N) { boundWarp = l; suffAbove[l] = above; }
    }
    __syncthreads();
    if (w == boundWarp) {
        unsigned running = suffAbove[w];
        for (int c = 255; c >= 0; c--) {
            unsigned h = g_hist[seg + c * 32 + l];
            unsigned suf = h;                 // suffix over lanes >= l
            #pragma unroll
            for (int d = 1; d < 32; d <<= 1) {
                unsigned v = __shfl_down_sync(0xFFFFFFFFu, suf, d);
                if (l + d < 32) suf += v;
            }
            unsigned bal = __ballot_sync(0xFFFFFFFFu, running + suf >= PRE_N);
            if (bal) {
                if (l == 0) {
                    int lb = 31 - __clz(bal);          // highest qualifying lane
                    unsigned bin = (unsigned)(seg + c * 32 + lb);
                    g_thresh = bin << BIN_SHIFT;
                }
                break;
            }
            running += __shfl_sync(0xFFFFFFFFu, suf, 0);   // whole-chunk total
        }
    }
}

// ---------------- 3) collect candidates (transposed idx = pos*3 + a) --------
__global__ void k_collect(const float4* __restrict__ sc) {
    unsigned T = g_thresh;
    int t = blockIdx.x * blockDim.x + threadIdx.x;
    float4 v = __ldg(&sc[t]);
    int base = 4 * t;
    int a = base / CH_STRIDE;            // all 4 elements share the channel
    int pos = base - a * CH_STRIDE;
    unsigned k0 = mapKey(v.x), k1 = mapKey(v.y), k2 = mapKey(v.z), k3 = mapKey(v.w);
    if (k0 >= T) { unsigned p = atomicAdd(&g_candCount, 1u); if (p < CAND_CAP) g_cand[p] = ((unsigned long long)(~k0) << 32) | (unsigned)((pos + 0) * 3 + a); }
    if (k1 >= T) { unsigned p = atomicAdd(&g_candCount, 1u); if (p < CAND_CAP) g_cand[p] = ((unsigned long long)(~k1) << 32) | (unsigned)((pos + 1) * 3 + a); }
    if (k2 >= T) { unsigned p = atomicAdd(&g_candCount, 1u); if (p < CAND_CAP) g_cand[p] = ((unsigned long long)(~k2) << 32) | (unsigned)((pos + 2) * 3 + a); }
    if (k3 >= T) { unsigned p = atomicAdd(&g_candCount, 1u); if (p < CAND_CAP) g_cand[p] = ((unsigned long long)(~k3) << 32) | (unsigned)((pos + 3) * 3 + a); }
}

// ---------------- 4) rank-and-scatter: 128 blocks, warp-per-4-keys ----------
__global__ void k_rank() {
    __shared__ unsigned long long sKeys[CAND_CAP];
    int tid = threadIdx.x;
    int cc = (int)g_candCount; if (cc > CAND_CAP) cc = CAND_CAP;
    for (int i = tid; i < cc; i += 256) sKeys[i] = g_cand[i];
    __syncthreads();
    int w = tid >> 5, l = tid & 31;
    int kbase = blockIdx.x * 32 + w * 4;      // this warp owns keys kbase..+3
    if (kbase >= cc) return;
    unsigned long long k0 = sKeys[kbase];
    unsigned long long k1 = (kbase + 1 < cc) ? sKeys[kbase + 1] : 0xFFFFFFFFFFFFFFFFULL;
    unsigned long long k2 = (kbase + 2 < cc) ? sKeys[kbase + 2] : 0xFFFFFFFFFFFFFFFFULL;
    unsigned long long k3 = (kbase + 3 < cc) ? sKeys[kbase + 3] : 0xFFFFFFFFFFFFFFFFULL;
    int r0 = 0, r1 = 0, r2 = 0, r3 = 0;
    for (int j = l; j < cc; j += 32) {
        unsigned long long kj = sKeys[j];
        r0 += (kj < k0); r1 += (kj < k1); r2 += (kj < k2); r3 += (kj < k3);
    }
    #pragma unroll
    for (int d = 16; d > 0; d >>= 1) {
        r0 += __shfl_down_sync(0xFFFFFFFFu, r0, d);
        r1 += __shfl_down_sync(0xFFFFFFFFu, r1, d);
        r2 += __shfl_down_sync(0xFFFFFFFFu, r2, d);
        r3 += __shfl_down_sync(0xFFFFFFFFu, r3, d);
    }
    if (l == 0) {
        if (r0 < PRE_N)                    g_topIdx[r0] = (int)(k0 & 0xFFFFFFFFu);
        if (kbase + 1 < cc && r1 < PRE_N)  g_topIdx[r1] = (int)(k1 & 0xFFFFFFFFu);
        if (kbase + 2 < cc && r2 < PRE_N)  g_topIdx[r2] = (int)(k2 & 0xFFFFFFFFu);
        if (kbase + 3 < cc && r3 < PRE_N)  g_topIdx[r3] = (int)(k3 & 0xFFFFFFFFu);
    }
}

// ---------------- 5) box decode + validity ----------------------------------
__global__ void k_transform(const float* __restrict__ sc,
                            const float* __restrict__ dl,
                            const float* __restrict__ imi,
                            const float* __restrict__ anc) {
    int r = blockIdx.x * blockDim.x + threadIdx.x;    // 8x256 covers 2048
    bool valid = false;
    if (r < PRE_N) {
        int idx = g_topIdx[r];            // transposed flat index
        int a   = idx % 3;
        int pos = idx / 3;
        int wl  = pos % W_DIM;
        int hl  = (pos / W_DIM) % H_DIM;
        int sl  = pos / (W_DIM * H_DIM);
        float shx = wl * 4.0f, shy = hl * 4.0f, shz = sl * 4.0f;
        float ax1 = anc[a*6+0] + shx, ay1 = anc[a*6+1] + shy, az1 = anc[a*6+2] + shz;
        float ax2 = anc[a*6+3] + shx, ay2 = anc[a*6+4] + shy, az2 = anc[a*6+5] + shz;

        const float* db = dl + (size_t)(6 * a) * CH_STRIDE + pos;
        float d0 = db[0];
        float d1 = db[(size_t)CH_STRIDE];
        float d2 = db[(size_t)2 * CH_STRIDE];
        float d3 = db[(size_t)3 * CH_STRIDE];
        float d4 = db[(size_t)4 * CH_STRIDE];
        float d5 = db[(size_t)5 * CH_STRIDE];

        float w_ = ax2 - ax1 + 1.0f, h_ = ay2 - ay1 + 1.0f, dd = az2 - az1 + 1.0f;
        float cx = ax1 + 0.5f * w_, cy = ay1 + 0.5f * h_, cz = az1 + 0.5f * dd;
        float pcx = d0 * w_ + cx, pcy = d1 * h_ + cy, pcz = d2 * dd + cz;
        float pw = expf(d3) * w_, ph = expf(d4) * h_, pd = expf(d5) * dd;

        float slices = imi[0], height = imi[1], width = imi[2], scale = imi[3];
        float x1 = fminf(fmaxf(pcx - 0.5f * pw, 0.0f), width  - 1.0f);
        float y1 = fminf(fmaxf(pcy - 0.5f * ph, 0.0f), height - 1.0f);
        float z1 = fminf(fmaxf(pcz - 0.5f * pd, 0.0f), slices - 1.0f);
        float x2 = fminf(fmaxf(pcx + 0.5f * pw - 1.0f, 0.0f), width  - 1.0f);
        float y2 = fminf(fmaxf(pcy + 0.5f * ph - 1.0f, 0.0f), height - 1.0f);
        float z2 = fminf(fmaxf(pcz + 0.5f * pd - 1.0f, 0.0f), slices - 1.0f);

        g_bx1[r] = x1; g_by1[r] = y1; g_bz1[r] = z1;
        g_bx2[r] = x2; g_by2[r] = y2; g_bz2[r] = z2;
        g_vol[r] = (x2 - x1 + 1.0f) * (y2 - y1 + 1.0f) * (z2 - z1 + 1.0f);
        g_sc[r]  = sc[(size_t)a * CH_STRIDE + pos];

        float ss = x2 - x1 + 1.0f;
        float xc = x1 + ss * 0.5f, yc = y1 + ss * 0.5f, zc = z1 + ss * 0.5f;
        valid = (ss >= 8.0f * scale) && (xc < width) && (yc < height) && (zc < slices);
    }
    unsigned suppressed = __ballot_sync(0xFFFFFFFFu, !valid);
    if ((threadIdx.x & 31) == 0) g_supp32[r >> 5] = suppressed;
}

// ---------------- 6) IoU suppression bitmask + hist re-zero ------------------
__global__ void k_mask() {
    int by = blockIdx.y, bx = blockIdx.x;
    int t = threadIdx.x;
    // re-zero histogram for next replay: 1024 blocks x 64 thr x 4 = 262144
    {
        int gt = (by * 32 + bx) * 64 + t;
        #pragma unroll
        for (int k = 0; k < 4; k++) g_hist[gt + k * 65536] = 0u;
    }
    if (bx < by) {                       // whole tile has j < i
        int i = by * 64 + t;
        if (i < PRE_N) g_mask[(size_t)i * 32 + bx] = 0ULL;
        return;
    }
    __shared__ float cx1[64], cy1[64], cz1[64], cx2[64], cy2[64], cz2[64], cv[64];
    int j = bx * 64 + t;
    if (j < PRE_N) {
        cx1[t] = g_bx1[j]; cy1[t] = g_by1[j]; cz1[t] = g_bz1[j];
        cx2[t] = g_bx2[j]; cy2[t] = g_by2[j]; cz2[t] = g_bz2[j];
        cv[t]  = g_vol[j];
    }
    __syncthreads();
    int i = by * 64 + t;
    if (i >= PRE_N) return;
    float x1 = g_bx1[i], y1 = g_by1[i], z1 = g_bz1[i];
    float x2 = g_bx2[i], y2 = g_by2[i], z2 = g_bz2[i];
    float v  = g_vol[i];
    unsigned long long m = 0ULL;
    int jmax = PRE_N - bx * 64; if (jmax > 64) jmax = 64;
    for (int c = 0; c < jmax; c++) {
        int jg = bx * 64 + c;
        if (jg <= i) continue;
        float iw = fmaxf(fminf(x2, cx2[c]) - fmaxf(x1, cx1[c]) + 1.0f, 0.0f);
        float ih = fmaxf(fminf(y2, cy2[c]) - fmaxf(y1, cy1[c]) + 1.0f, 0.0f);
        float id = fmaxf(fminf(z2, cz2[c]) - fmaxf(z1, cz1[c]) + 1.0f, 0.0f);
        float inter = iw * ih * id;
        float iou = inter / (v + cv[c] - inter);
        if (iou > NMS_T) m |= (1ULL << c);
    }
    g_mask[(size_t)i * 32 + bx] = m;
}

// ---------------- 7) greedy reduce (smem-cached rows) + output --------------
__global__ void k_reduceout(float* __restrict__ out, int out_size) {
    extern __shared__ unsigned long long rowsSm[];    // CACHE_N * 32
    __shared__ int sKeep[POST_N];
    __shared__ int sKept;
    int t = threadIdx.x;                              // 1024 threads
    for (int w = t; w < CACHE_N * 32; w += 1024) rowsSm[w] = g_mask[w];
    __syncthreads();
    if (t < 32) {
        int lane = t;
        unsigned long long remv =
            ((unsigned long long)g_supp32[2 * lane + 1] << 32) | g_supp32[2 * lane];
        int kept = 0;
        for (int i = 0; i < PRE_N; i++) {
            unsigned long long w = __shfl_sync(0xFFFFFFFFu, remv, i >> 6);
            if (!((w >> (i & 63)) & 1ULL)) {
                remv |= (i < CACHE_N) ? rowsSm[i * 32 + lane]
                                      : g_mask[(size_t)i * 32 + lane];
                if (lane == 0) sKeep[kept] = i;
                kept++;
                if (kept == POST_N) break;
            }
        }
        if (lane == 0) sKept = kept;
    }
    __syncthreads();
    int kept = sKept;
    for (int s = t; s < POST_N; s += 1024) {
        float b0, b1, b2, b3, b4, b5, scv, kidx, vld;
        if (s < kept) {
            int i = sKeep[s];
            b0 = g_bx1[i]; b1 = g_by1[i]; b2 = g_bz1[i];
            b3 = g_bx2[i]; b4 = g_by2[i]; b5 = g_bz2[i];
            scv = g_sc[i]; kidx = (float)g_topIdx[i]; vld = 1.0f;
        } else {
            b0 = b1 = b2 = b3 = b4 = b5 = 0.0f;
            scv = 0.0f; kidx = -1.0f; vld = 0.0f;
        }
        int base = s * 7;
        out[base + 0] = 0.0f;
        out[base + 1] = b0; out[base + 2] = b1; out[base + 3] = b2;
        out[base + 4] = b3; out[base + 5] = b4; out[base + 6] = b5;
        if (out_size >= POST_N * 7 + POST_N) out[POST_N * 7 + s] = scv;
        if (out_size >= POST_N * 8 + POST_N) out[POST_N * 8 + s] = kidx;
        if (out_size >= POST_N * 9 + POST_N) out[POST_N * 9 + s] = vld;
    }
}

// ---------------- launcher --------------------------------------------------
extern "C" void kernel_launch(void* const* d_in, const int* in_sizes, int n_in,
                              void* d_out, int out_size) {
    const float*  sc  = (const float*)d_in[0];
    const float4* sc4 = (const float4*)d_in[0];
    const float*  dl  = (const float*)d_in[1];
    const float*  imi = (const float*)d_in[2];
    const float*  anc = (const float*)d_in[3];
    float* out = (float*)d_out;

    cudaFuncSetAttribute(k_reduceout, cudaFuncAttributeMaxDynamicSharedMemorySize,
                         CACHE_N * 32 * (int)sizeof(unsigned long long));

    k_hist     <<<NQ / 256, 256>>>(sc4);
    k_scan     <<<1, 1024>>>();
    k_collect  <<<NQ / 256, 256>>>(sc4);
    k_rank     <<<128, 256>>>();
    k_transform<<<8, 256>>>(sc, dl, imi, anc);
    k_mask     <<<dim3(32, 32), 64>>>();
    k_reduceout<<<1, 1024, CACHE_N * 32 * sizeof(unsigned long long)>>>(out, out_size);
}

// round 14
// speedup vs baseline: 1.7360x; 1.0521x over previous
#include <cuda_runtime.h>

#define NTOT       1572864      // 3 * 32 * 128 * 128 scores
#define NQ         393216       // NTOT / 4
#define W_DIM      128
#define H_DIM      128
#define CH_STRIDE  524288       // 32*128*128 (per-channel stride)
#define PRE_N      2000
#define POST_N     300
#define CAND_CAP   4096
#define NMS_T      0.7f
#define CACHE_N    640          // mask rows cached in smem for reduce
#define HBINS      262144       // 2^18 coarse bins
#define BIN_SHIFT  14           // key >> 14 -> bin

// ---------------- scratch (device globals; zero-initialized at load) -------
__device__ unsigned g_hist[HBINS];
__device__ unsigned g_thresh;
__device__ unsigned g_candCount;
__device__ unsigned long long g_cand[CAND_CAP];
__device__ int g_topIdx[PRE_N];

__device__ float g_bx1[PRE_N], g_by1[PRE_N], g_bz1[PRE_N];
__device__ float g_bx2[PRE_N], g_by2[PRE_N], g_bz2[PRE_N];
__device__ float g_vol[PRE_N], g_sc[PRE_N];

__device__ unsigned g_supp32[64];                 // initial suppression bits
__device__ unsigned long long g_mask[PRE_N * 32]; // NMS suppression bitmask rows

__device__ __forceinline__ unsigned mapKey(float f) {
    unsigned b = __float_as_uint(f);
    return b ^ ((b & 0x80000000u) ? 0xFFFFFFFFu : 0x80000000u);
}

// ---------------- 1) coarse 18-bit histogram --------------------------------
__global__ void k_hist(const float4* __restrict__ sc) {
    int t = blockIdx.x * blockDim.x + threadIdx.x;   // 0..NQ-1 exactly
    float4 v = __ldg(&sc[t]);
    atomicAdd(&g_hist[mapKey(v.x) >> BIN_SHIFT], 1u);
    atomicAdd(&g_hist[mapKey(v.y) >> BIN_SHIFT], 1u);
    atomicAdd(&g_hist[mapKey(v.z) >> BIN_SHIFT], 1u);
    atomicAdd(&g_hist[mapKey(v.w) >> BIN_SHIFT], 1u);
}

// ---------------- 2) find boundary bin (coalesced, warp-segmented) ----------
__global__ void k_scan() {
    __shared__ unsigned warpTot[32];
    __shared__ unsigned suffAbove[32];
    __shared__ int boundWarp;
    int t = threadIdx.x;             // 1024 threads = 32 warps
    int w = t >> 5, l = t & 31;
    if (t == 0) { g_candCount = 0u; boundWarp = -1; }
    int seg = w * 8192;              // warp w owns bins [seg, seg+8192)
    unsigned s = 0;
    #pragma unroll 16
    for (int i = 0; i < 256; i++) s += g_hist[seg + i * 32 + l];   // coalesced
    #pragma unroll
    for (int d = 16; d > 0; d >>= 1) s += __shfl_down_sync(0xFFFFFFFFu, s, d);
    if (l == 0) warpTot[w] = s;
    __syncthreads();
    if (w == 0) {
        unsigned tot = warpTot[l];
        unsigned suf = tot;
        #pragma unroll
        for (int d = 1; d < 32; d <<= 1) {
            unsigned v = __shfl_down_sync(0xFFFFFFFFu, suf, d);
            if (l + d < 32) suf += v;
        }
        unsigned above = suf - tot;
        if (above < PRE_N && suf >= PRE_N) { boundWarp = l; suffAbove[l] = above; }
    }
    __syncthreads();
    if (w == boundWarp) {
        unsigned running = suffAbove[w];
        for (int c = 255; c >= 0; c--) {
            unsigned h = g_hist[seg + c * 32 + l];
            unsigned suf = h;                 // suffix over lanes >= l
            #pragma unroll
            for (int d = 1; d < 32; d <<= 1) {
                unsigned v = __shfl_down_sync(0xFFFFFFFFu, suf, d);
                if (l + d < 32) suf += v;
            }
            unsigned bal = __ballot_sync(0xFFFFFFFFu, running + suf >= PRE_N);
            if (bal) {
                if (l == 0) {
                    int lb = 31 - __clz(bal);          // highest qualifying lane
                    unsigned bin = (unsigned)(seg + c * 32 + lb);
                    g_thresh = bin << BIN_SHIFT;
                }
                break;
            }
            running += __shfl_sync(0xFFFFFFFFu, suf, 0);   // whole-chunk total
        }
    }
}

// ---------------- 3) collect candidates (transposed idx = pos*3 + a) --------
__global__ void k_collect(const float4* __restrict__ sc) {
    unsigned T = g_thresh;
    int t = blockIdx.x * blockDim.x + threadIdx.x;
    float4 v = __ldg(&sc[t]);
    int base = 4 * t;
    int a = base / CH_STRIDE;            // all 4 elements share the channel
    int pos = base - a * CH_STRIDE;
    unsigned k0 = mapKey(v.x), k1 = mapKey(v.y), k2 = mapKey(v.z), k3 = mapKey(v.w);
    if (k0 >= T) { unsigned p = atomicAdd(&g_candCount, 1u); if (p < CAND_CAP) g_cand[p] = ((unsigned long long)(~k0) << 32) | (unsigned)((pos + 0) * 3 + a); }
    if (k1 >= T) { unsigned p = atomicAdd(&g_candCount, 1u); if (p < CAND_CAP) g_cand[p] = ((unsigned long long)(~k1) << 32) | (unsigned)((pos + 1) * 3 + a); }
    if (k2 >= T) { unsigned p = atomicAdd(&g_candCount, 1u); if (p < CAND_CAP) g_cand[p] = ((unsigned long long)(~k2) << 32) | (unsigned)((pos + 2) * 3 + a); }
    if (k3 >= T) { unsigned p = atomicAdd(&g_candCount, 1u); if (p < CAND_CAP) g_cand[p] = ((unsigned long long)(~k3) << 32) | (unsigned)((pos + 3) * 3 + a); }
}

// ---------------- 4) rank-and-scatter: 128 blocks, warp-per-4-keys ----------
__global__ void k_rank() {
    __shared__ unsigned long long sKeys[CAND_CAP];
    int tid = threadIdx.x;
    int cc = (int)g_candCount; if (cc > CAND_CAP) cc = CAND_CAP;
    for (int i = tid; i < cc; i += 256) sKeys[i] = g_cand[i];
    __syncthreads();
    int w = tid >> 5, l = tid & 31;
    int kbase = blockIdx.x * 32 + w * 4;      // this warp owns keys kbase..+3
    if (kbase >= cc) return;
    unsigned long long k0 = sKeys[kbase];
    unsigned long long k1 = (kbase + 1 < cc) ? sKeys[kbase + 1] : 0xFFFFFFFFFFFFFFFFULL;
    unsigned long long k2 = (kbase + 2 < cc) ? sKeys[kbase + 2] : 0xFFFFFFFFFFFFFFFFULL;
    unsigned long long k3 = (kbase + 3 < cc) ? sKeys[kbase + 3] : 0xFFFFFFFFFFFFFFFFULL;
    int r0 = 0, r1 = 0, r2 = 0, r3 = 0;
    for (int j = l; j < cc; j += 32) {
        unsigned long long kj = sKeys[j];
        r0 += (kj < k0); r1 += (kj < k1); r2 += (kj < k2); r3 += (kj < k3);
    }
    #pragma unroll
    for (int d = 16; d > 0; d >>= 1) {
        r0 += __shfl_down_sync(0xFFFFFFFFu, r0, d);
        r1 += __shfl_down_sync(0xFFFFFFFFu, r1, d);
        r2 += __shfl_down_sync(0xFFFFFFFFu, r2, d);
        r3 += __shfl_down_sync(0xFFFFFFFFu, r3, d);
    }
    if (l == 0) {
        if (r0 < PRE_N)                    g_topIdx[r0] = (int)(k0 & 0xFFFFFFFFu);
        if (kbase + 1 < cc && r1 < PRE_N)  g_topIdx[r1] = (int)(k1 & 0xFFFFFFFFu);
        if (kbase + 2 < cc && r2 < PRE_N)  g_topIdx[r2] = (int)(k2 & 0xFFFFFFFFu);
        if (kbase + 3 < cc && r3 < PRE_N)  g_topIdx[r3] = (int)(k3 & 0xFFFFFFFFu);
    }
}

// ---------------- 5) box decode + validity ----------------------------------
__global__ void k_transform(const float* __restrict__ sc,
                            const float* __restrict__ dl,
                            const float* __restrict__ imi,
                            const float* __restrict__ anc) {
    int r = blockIdx.x * blockDim.x + threadIdx.x;    // 8x256 covers 2048
    bool valid = false;
    if (r < PRE_N) {
        int idx = g_topIdx[r];            // transposed flat index
        int a   = idx % 3;
        int pos = idx / 3;
        int wl  = pos % W_DIM;
        int hl  = (pos / W_DIM) % H_DIM;
        int sl  = pos / (W_DIM * H_DIM);
        float shx = wl * 4.0f, shy = hl * 4.0f, shz = sl * 4.0f;
        float ax1 = anc[a*6+0] + shx, ay1 = anc[a*6+1] + shy, az1 = anc[a*6+2] + shz;
        float ax2 = anc[a*6+3] + shx, ay2 = anc[a*6+4] + shy, az2 = anc[a*6+5] + shz;

        const float* db = dl + (size_t)(6 * a) * CH_STRIDE + pos;
        float d0 = db[0];
        float d1 = db[(size_t)CH_STRIDE];
        float d2 = db[(size_t)2 * CH_STRIDE];
        float d3 = db[(size_t)3 * CH_STRIDE];
        float d4 = db[(size_t)4 * CH_STRIDE];
        float d5 = db[(size_t)5 * CH_STRIDE];

        float w_ = ax2 - ax1 + 1.0f, h_ = ay2 - ay1 + 1.0f, dd = az2 - az1 + 1.0f;
        float cx = ax1 + 0.5f * w_, cy = ay1 + 0.5f * h_, cz = az1 + 0.5f * dd;
        float pcx = d0 * w_ + cx, pcy = d1 * h_ + cy, pcz = d2 * dd + cz;
        float pw = expf(d3) * w_, ph = expf(d4) * h_, pd = expf(d5) * dd;

        float slices = imi[0], height = imi[1], width = imi[2], scale = imi[3];
        float x1 = fminf(fmaxf(pcx - 0.5f * pw, 0.0f), width  - 1.0f);
        float y1 = fminf(fmaxf(pcy - 0.5f * ph, 0.0f), height - 1.0f);
        float z1 = fminf(fmaxf(pcz - 0.5f * pd, 0.0f), slices - 1.0f);
        float x2 = fminf(fmaxf(pcx + 0.5f * pw - 1.0f, 0.0f), width  - 1.0f);
        float y2 = fminf(fmaxf(pcy + 0.5f * ph - 1.0f, 0.0f), height - 1.0f);
        float z2 = fminf(fmaxf(pcz + 0.5f * pd - 1.0f, 0.0f), slices - 1.0f);

        g_bx1[r] = x1; g_by1[r] = y1; g_bz1[r] = z1;
        g_bx2[r] = x2; g_by2[r] = y2; g_bz2[r] = z2;
        g_vol[r] = (x2 - x1 + 1.0f) * (y2 - y1 + 1.0f) * (z2 - z1 + 1.0f);
        g_sc[r]  = sc[(size_t)a * CH_STRIDE + pos];

        float ss = x2 - x1 + 1.0f;
        float xc = x1 + ss * 0.5f, yc = y1 + ss * 0.5f, zc = z1 + ss * 0.5f;
        valid = (ss >= 8.0f * scale) && (xc < width) && (yc < height) && (zc < slices);
    }
    unsigned suppressed = __ballot_sync(0xFFFFFFFFu, !valid);
    if ((threadIdx.x & 31) == 0) g_supp32[r >> 5] = suppressed;
}

// ---------------- 6) IoU suppression bitmask + hist re-zero ------------------
__global__ void k_mask() {
    int by = blockIdx.y, bx = blockIdx.x;
    int t = threadIdx.x;
    // re-zero histogram for next replay: 1024 blocks x 64 thr x 4 = 262144
    {
        int gt = (by * 32 + bx) * 64 + t;
        #pragma unroll
        for (int k = 0; k < 4; k++) g_hist[gt + k * 65536] = 0u;
    }
    if (bx < by) {                       // whole tile has j < i
        int i = by * 64 + t;
        if (i < PRE_N) g_mask[(size_t)i * 32 + bx] = 0ULL;
        return;
    }
    __shared__ float cx1[64], cy1[64], cz1[64], cx2[64], cy2[64], cz2[64], cv[64];
    int j = bx * 64 + t;
    if (j < PRE_N) {
        cx1[t] = g_bx1[j]; cy1[t] = g_by1[j]; cz1[t] = g_bz1[j];
        cx2[t] = g_bx2[j]; cy2[t] = g_by2[j]; cz2[t] = g_bz2[j];
        cv[t]  = g_vol[j];
    }
    __syncthreads();
    int i = by * 64 + t;
    if (i >= PRE_N) return;
    float x1 = g_bx1[i], y1 = g_by1[i], z1 = g_bz1[i];
    float x2 = g_bx2[i], y2 = g_by2[i], z2 = g_bz2[i];
    float v  = g_vol[i];
    unsigned long long m = 0ULL;
    int jmax = PRE_N - bx * 64; if (jmax > 64) jmax = 64;
    for (int c = 0; c < jmax; c++) {
        int jg = bx * 64 + c;
        if (jg <= i) continue;
        float iw = fmaxf(fminf(x2, cx2[c]) - fmaxf(x1, cx1[c]) + 1.0f, 0.0f);
        float ih = fmaxf(fminf(y2, cy2[c]) - fmaxf(y1, cy1[c]) + 1.0f, 0.0f);
        float id = fmaxf(fminf(z2, cz2[c]) - fmaxf(z1, cz1[c]) + 1.0f, 0.0f);
        float inter = iw * ih * id;
        // iou > T  <=>  inter > T * union   (union > 0; avoids MUFU division)
        if (inter > NMS_T * (v + cv[c] - inter)) m |= (1ULL << c);
    }
    g_mask[(size_t)i * 32 + bx] = m;
}

// ---------------- 7) greedy reduce (cached-word chain) + output -------------
__global__ void k_reduceout(float* __restrict__ out, int out_size) {
    extern __shared__ unsigned long long rowsSm[];    // CACHE_N * 32
    __shared__ int sKeep[POST_N];
    __shared__ int sKept;
    int t = threadIdx.x;                              // 1024 threads
    for (int w = t; w < CACHE_N * 32; w += 1024) rowsSm[w] = g_mask[w];
    __syncthreads();
    if (t < 32) {
        int lane = t;
        unsigned long long remv =
            ((unsigned long long)g_supp32[2 * lane + 1] << 32) | g_supp32[2 * lane];
        int kept = 0;
        int curWI = 0;
        unsigned long long curw = __shfl_sync(0xFFFFFFFFu, remv, 0);
        for (int i = 0; i < PRE_N; i++) {
            int wi = i >> 6;
            if (wi != curWI) {                       // word crossing: re-broadcast
                curw = __shfl_sync(0xFFFFFFFFu, remv, wi);
                curWI = wi;
            }
            if (!((curw >> (i & 63)) & 1ULL)) {      // keep i
                remv |= (i < CACHE_N) ? rowsSm[i * 32 + lane]
                                      : g_mask[(size_t)i * 32 + lane];
                curw = __shfl_sync(0xFFFFFFFFu, remv, wi);  // refresh after OR
                if (lane == 0) sKeep[kept] = i;
                kept++;
                if (kept == POST_N) break;
            }
        }
        if (lane == 0) sKept = kept;
    }
    __syncthreads();
    int kept = sKept;
    for (int s = t; s < POST_N; s += 1024) {
        float b0, b1, b2, b3, b4, b5, scv, kidx, vld;
        if (s < kept) {
            int i = sKeep[s];
            b0 = g_bx1[i]; b1 = g_by1[i]; b2 = g_bz1[i];
            b3 = g_bx2[i]; b4 = g_by2[i]; b5 = g_bz2[i];
            scv = g_sc[i]; kidx = (float)g_topIdx[i]; vld = 1.0f;
        } else {
            b0 = b1 = b2 = b3 = b4 = b5 = 0.0f;
            scv = 0.0f; kidx = -1.0f; vld = 0.0f;
        }
        int base = s * 7;
        out[base + 0] = 0.0f;
        out[base + 1] = b0; out[base + 2] = b1; out[base + 3] = b2;
        out[base + 4] = b3; out[base + 5] = b4; out[base + 6] = b5;
        if (out_size >= POST_N * 7 + POST_N) out[POST_N * 7 + s] = scv;
        if (out_size >= POST_N * 8 + POST_N) out[POST_N * 8 + s] = kidx;
        if (out_size >= POST_N * 9 + POST_N) out[POST_N * 9 + s] = vld;
    }
}

// ---------------- launcher --------------------------------------------------
extern "C" void kernel_launch(void* const* d_in, const int* in_sizes, int n_in,
                              void* d_out, int out_size) {
    const float*  sc  = (const float*)d_in[0];
    const float4* sc4 = (const float4*)d_in[0];
    const float*  dl  = (const float*)d_in[1];
    const float*  imi = (const float*)d_in[2];
    const float*  anc = (const float*)d_in[3];
    float* out = (float*)d_out;

    cudaFuncSetAttribute(k_reduceout, cudaFuncAttributeMaxDynamicSharedMemorySize,
                         CACHE_N * 32 * (int)sizeof(unsigned long long));

    k_hist     <<<NQ / 256, 256>>>(sc4);
    k_scan     <<<1, 1024>>>();
    k_collect  <<<NQ / 256, 256>>>(sc4);
    k_rank     <<<128, 256>>>();
    k_transform<<<8, 256>>>(sc, dl, imi, anc);
    k_mask     <<<dim3(32, 32), 64>>>();
    k_reduceout<<<1, 1024, CACHE_N * 32 * sizeof(unsigned long long)>>>(out, out_size);
}